// round 15
// baseline (speedup 1.0000x reference)
#include <cuda_runtime.h>

#define H 1024
#define V 50257
#define LCTX 4096

#define NBLK 888            // 148 SMs x 6 co-resident 256-thr blocks -> sw barrier safe
#define TPB  256
#define NWARP (NBLK * 8)    // 7104 warps
#define NROW_LOG 8          // ceil(V / NWARP), consecutive rows per warp

// ---------------- device scratch (allocation-free, 16B aligned) ----------------
__device__ __align__(16) float g_e[LCTX];
__device__ __align__(16) float g_cat[2 * H];
__device__ __align__(16) float g_x[H];
__device__ __align__(16) float g_gh[3 * H];
__device__ __align__(16) float g_h[H];
__device__ float g_bm[NBLK];
__device__ float g_bs[NBLK];
__device__ unsigned g_bar_count = 0;
__device__ unsigned g_bar_gen   = 0;

__device__ __forceinline__ void grid_barrier() {
    __threadfence();
    __syncthreads();
    if (threadIdx.x == 0) {
        unsigned gen = *(volatile unsigned*)&g_bar_gen;
        if (atomicAdd(&g_bar_count, 1u) == NBLK - 1) {
            g_bar_count = 0;
            __threadfence();
            atomicExch(&g_bar_gen, gen + 1);
        } else {
            while (*(volatile unsigned*)&g_bar_gen == gen) { __nanosleep(64); }
        }
        __threadfence();
    }
    __syncthreads();
}

__device__ __forceinline__ float warp_sum(float s) {
#pragma unroll
    for (int o = 16; o; o >>= 1) s += __shfl_xor_sync(0xffffffffu, s, o);
    return s;
}
__device__ __forceinline__ void pair_combine(float& m, float& s, float om, float os) {
    float nm = fmaxf(m, om);
    s = s * expf(m - nm) + os * expf(om - nm);
    m = nm;
}
__device__ __forceinline__ void warp_pair_reduce8(float& m, float& s) {
#pragma unroll
    for (int o = 4; o; o >>= 1) {
        float om = __shfl_xor_sync(0xffffffffu, m, o);
        float os = __shfl_xor_sync(0xffffffffu, s, o);
        pair_combine(m, s, om, os);
    }
}
__device__ __forceinline__ void warp_pair_reduce32(float& m, float& s) {
#pragma unroll
    for (int o = 16; o; o >>= 1) {
        float om = __shfl_xor_sync(0xffffffffu, m, o);
        float os = __shfl_xor_sync(0xffffffffu, s, o);
        pair_combine(m, s, om, os);
    }
}

template <int C4>
__device__ __forceinline__ float row_dot(const float4* __restrict__ row,
                                         const float4* __restrict__ vec, int lane) {
    float s = 0.0f;
#pragma unroll
    for (int i = 0; i < C4 / 32; ++i) {
        float4 w = __ldg(&row[lane + i * 32]);
        float4 x = vec[lane + i * 32];
        s = fmaf(w.x, x.x, s); s = fmaf(w.y, x.y, s);
        s = fmaf(w.z, x.z, s); s = fmaf(w.w, x.w, s);
    }
    return warp_sum(s);
}

// ================= everything in ONE kernel, 6 blocks/SM =================
__global__ void __launch_bounds__(TPB, 6)
fused_kernel(const int* __restrict__ y, const float* __restrict__ s_bef,
             const float* __restrict__ h_all, const float* __restrict__ emb_W,
             const float* __restrict__ alignW, const float* __restrict__ new_W,
             const float* __restrict__ new_b, const float* __restrict__ W_ih,
             const float* __restrict__ b_ih, const float* __restrict__ W_hh,
             const float* __restrict__ b_hh, const float* __restrict__ out_W,
             const float* __restrict__ out_b, float* __restrict__ out) {
    __shared__ float sbuf[2 * H];
    __shared__ float sred[40];
    __shared__ float smp[8], ssp[8];

    const int t    = threadIdx.x;
    const int bid  = blockIdx.x;
    const int wid  = t >> 5;
    const int lane = t & 31;
    const int gw   = bid * 8 + wid;     // 0..7103
    const int r0   = gw * NROW_LOG;     // this warp's phase-5 row base
    float4* sb4 = reinterpret_cast<float4*>(sbuf);

    // ---------- phase 1: e = h_all@Wh (online stats) ; gh = W_hh@s_prev + b_hh ; setup ----------
    sb4[t]       = reinterpret_cast<const float4*>(alignW)[t];        // Wh
    sb4[256 + t] = reinterpret_cast<const float4*>(s_bef)[t];         // s_prev
    __syncthreads();

    if (bid == 1)
        reinterpret_cast<float4*>(g_cat)[t] =
            reinterpret_cast<const float4*>(emb_W)[(size_t)y[0] * 256 + t];
    if (bid == 2)
        reinterpret_cast<float4*>(g_cat)[256 + t] = make_float4(0.f, 0.f, 0.f, 0.f);

    float em = -1e30f, es = 0.0f;                // this warp's online e-stats (fixed order)
    for (int r = gw; r < LCTX + 3 * H; r += NWARP) {
        float s;
        if (r < LCTX)
            s = row_dot<256>(reinterpret_cast<const float4*>(h_all) + (size_t)r * 256, sb4, lane);
        else
            s = row_dot<256>(reinterpret_cast<const float4*>(W_hh) + (size_t)(r - LCTX) * 256, sb4 + 256, lane);
        if (r < LCTX) {
            if (lane == 0) g_e[r] = s;
            pair_combine(em, es, s, 1.0f);       // s is warp-uniform after warp_sum
        } else if (lane == 0) {
            g_gh[r - LCTX] = s + b_hh[r - LCTX];
        }
    }
    if (lane == 0) { smp[wid] = em; ssp[wid] = es; }
    __syncthreads();
    if (wid == 0) {
        float pm = (lane < 8) ? smp[lane] : -1e30f;
        float ps = (lane < 8) ? ssp[lane] : 0.0f;
        warp_pair_reduce8(pm, ps);
        if (lane == 0) { g_bm[bid] = pm; g_bs[bid] = ps; }
    }
    grid_barrier();

    // ---------- phase 2: combine 888 e-stat pairs (fixed order) ; ctx ; a-out ----------
    {
        float pm = -1e30f, ps = 0.0f;
        for (int i = t; i < NBLK; i += TPB) pair_combine(pm, ps, g_bm[i], g_bs[i]);
        warp_pair_reduce32(pm, ps);
        if (lane == 0) { smp[wid] = pm; ssp[wid] = ps; }
        __syncthreads();
        if (wid == 0) {
            float qm = (lane < 8) ? smp[lane] : -1e30f;
            float qs = (lane < 8) ? ssp[lane] : 0.0f;
            warp_pair_reduce8(qm, qs);
            if (lane == 0) { sred[32] = qm; sred[33] = qs; }
        }
        __syncthreads();
    }
    const float M    = sred[32];
    const float invS = 1.0f / sred[33];
    __syncthreads();

    if (bid < 512) {
        // ctx: block = 32 l-rows x 256 cols; h_all re-read is L2-hot
        const int jg = bid & 3, l0 = (bid >> 2) * 32;
        if (t < 32) sbuf[t] = expf(g_e[l0 + t] - M) * invS;
        __syncthreads();
        const int j = jg * 256 + t;
        const float* hp = h_all + (size_t)l0 * H + j;
        float acc = 0.0f;
#pragma unroll 8
        for (int l = 0; l < 32; ++l) acc = fmaf(sbuf[l], hp[(size_t)l * H], acc);
        atomicAdd(&g_cat[H + j], acc);
    } else if (bid < 528) {
        int l = (bid - 512) * 256 + t;
        out[V + H + l] = expf(g_e[l] - M) * invS;   // attention weights output
    }
    grid_barrier();

    // ---------- phase 3: x = new_W @ [emb; c] + new_b ----------
    if (bid < 128) {
        sb4[t]       = reinterpret_cast<const float4*>(g_cat)[t];
        sb4[256 + t] = reinterpret_cast<const float4*>(g_cat)[256 + t];
        __syncthreads();
        float acc = row_dot<512>(reinterpret_cast<const float4*>(new_W) + (size_t)gw * 512, sb4, lane);
        if (lane == 0) g_x[gw] = acc + new_b[gw];
    }
    grid_barrier();

    // ---------- phase 4: gi rows (3 per warp) fused with GRU gates -> h_new ----------
    if (bid < 128) {
        sb4[t] = reinterpret_cast<const float4*>(g_x)[t];
        __syncthreads();
        const float4* Wv = reinterpret_cast<const float4*>(W_ih);
        float d0 = row_dot<256>(Wv + (size_t)gw * 256, sb4, lane);
        float d1 = row_dot<256>(Wv + (size_t)(gw + H) * 256, sb4, lane);
        float d2 = row_dot<256>(Wv + (size_t)(gw + 2 * H) * 256, sb4, lane);
        if (lane == 0) {
            float rr = 1.0f / (1.0f + expf(-(d0 + b_ih[gw] + g_gh[gw])));
            float zz = 1.0f / (1.0f + expf(-(d1 + b_ih[gw + H] + g_gh[gw + H])));
            float nn = tanhf(d2 + b_ih[gw + 2 * H] + rr * g_gh[gw + 2 * H]);
            float hv = (1.0f - zz) * nn + zz * s_bef[gw];
            g_h[gw]    = hv;
            out[V + gw] = hv;
        }
    }
    grid_barrier();

    // ---------- phase 5: logits GEMV, 8 consecutive rows/warp, __ldcs stream ----------
    sb4[t] = reinterpret_cast<const float4*>(g_h)[t];
    __syncthreads();

    float vals[NROW_LOG];
#pragma unroll
    for (int k = 0; k < NROW_LOG; ++k) {
        const int r = r0 + k;
        float s = 0.0f;
        if (r < V) {
            const float4* Wr = reinterpret_cast<const float4*>(out_W) + (size_t)r * 256;
#pragma unroll
            for (int i = 0; i < 8; ++i) {
                float4 w = __ldcs(&Wr[lane + i * 32]);
                float4 x = sb4[lane + i * 32];
                s = fmaf(w.x, x.x, s); s = fmaf(w.y, x.y, s);
                s = fmaf(w.z, x.z, s); s = fmaf(w.w, x.w, s);
            }
        }
        vals[k] = s;
    }
#pragma unroll
    for (int k = 0; k < NROW_LOG; ++k) {
        vals[k] = warp_sum(vals[k]);
        if (r0 + k < V) vals[k] += out_b[r0 + k];
    }
    float lm = -1e30f, ls = 0.0f;
#pragma unroll
    for (int k = 0; k < NROW_LOG; ++k)
        if (r0 + k < V) pair_combine(lm, ls, vals[k], 1.0f);

    if (lane == 0) { smp[wid] = lm; ssp[wid] = ls; }
    __syncthreads();
    if (wid == 0) {
        float pm = (lane < 8) ? smp[lane] : -1e30f;
        float ps = (lane < 8) ? ssp[lane] : 0.0f;
        warp_pair_reduce8(pm, ps);
        if (lane == 0) { g_bm[bid] = pm; g_bs[bid] = ps; }
    }
    grid_barrier();

    // ---------- phase 6: combine 888 block pairs redundantly; store final logp ----------
    {
        float pm = -1e30f, ps = 0.0f;
        for (int i = t; i < NBLK; i += TPB) pair_combine(pm, ps, g_bm[i], g_bs[i]);
        warp_pair_reduce32(pm, ps);
        if (lane == 0) { smp[wid] = pm; ssp[wid] = ps; }
        __syncthreads();
        if (wid == 0) {
            float qm = (lane < 8) ? smp[lane] : -1e30f;
            float qs = (lane < 8) ? ssp[lane] : 0.0f;
            warp_pair_reduce8(qm, qs);
            if (lane == 0) sred[34] = qm + logf(qs);
        }
        __syncthreads();
        const float ln = sred[34];
        if (lane == 0) {
#pragma unroll
            for (int k = 0; k < NROW_LOG; ++k)
                if (r0 + k < V) out[r0 + k] = vals[k] - ln;   // only store of logits
        }
    }
}

// ================= launch: single kernel =================
extern "C" void kernel_launch(void* const* d_in, const int* in_sizes, int n_in,
                              void* d_out, int out_size) {
    const int*   y      = (const int*)d_in[0];
    const float* s_bef  = (const float*)d_in[1];
    const float* h_all  = (const float*)d_in[2];
    const float* emb_W  = (const float*)d_in[3];
    const float* alignW = (const float*)d_in[4];
    // d_in[5] align_b: uniform additive shift -> softmax-invariant, dropped
    const float* new_W  = (const float*)d_in[6];
    const float* new_b  = (const float*)d_in[7];
    const float* W_ih   = (const float*)d_in[8];
    const float* b_ih   = (const float*)d_in[9];
    const float* W_hh   = (const float*)d_in[10];
    const float* b_hh   = (const float*)d_in[11];
    const float* out_W  = (const float*)d_in[12];
    const float* out_b  = (const float*)d_in[13];
    float* out = (float*)d_out;  // [logp(V) | h_new(H) | a(L)]

    fused_kernel<<<NBLK, TPB>>>(y, s_bef, h_all, emb_W, alignW, new_W, new_b,
                                W_ih, b_ih, W_hh, b_hh, out_W, out_b, out);
}

// round 16
// speedup vs baseline: 1.0616x; 1.0616x over previous
#include <cuda_runtime.h>

#define H 1024
#define V 50257
#define LCTX 4096

#define NBLK 740            // 148 SMs x 5 co-resident 256-thr blocks -> sw barrier safe
#define TPB  256
#define NWARP (NBLK * 8)    // 5920 warps
#define NROW_LOG 9          // ceil(V / NWARP), consecutive rows per warp

// ---------------- device scratch (allocation-free, 16B aligned) ----------------
__device__ __align__(16) float g_e[LCTX];
__device__ __align__(16) float g_cat[2 * H];
__device__ __align__(16) float g_x[H];
__device__ __align__(16) float g_gh[3 * H];
__device__ __align__(16) float g_h[H];
__device__ float g_bm[NBLK];
__device__ float g_bs[NBLK];
__device__ unsigned g_bar_count = 0;
__device__ unsigned g_bar_gen   = 0;

__device__ __forceinline__ void grid_barrier() {
    __threadfence();
    __syncthreads();
    if (threadIdx.x == 0) {
        unsigned gen = *(volatile unsigned*)&g_bar_gen;
        if (atomicAdd(&g_bar_count, 1u) == NBLK - 1) {
            g_bar_count = 0;
            __threadfence();
            atomicExch(&g_bar_gen, gen + 1);
        } else {
            while (*(volatile unsigned*)&g_bar_gen == gen) { __nanosleep(64); }
        }
        __threadfence();
    }
    __syncthreads();
}

__device__ __forceinline__ float warp_sum(float s) {
#pragma unroll
    for (int o = 16; o; o >>= 1) s += __shfl_xor_sync(0xffffffffu, s, o);
    return s;
}
__device__ __forceinline__ void pair_combine(float& m, float& s, float om, float os) {
    float nm = fmaxf(m, om);
    s = s * expf(m - nm) + os * expf(om - nm);
    m = nm;
}
__device__ __forceinline__ void warp_pair_reduce8(float& m, float& s) {
#pragma unroll
    for (int o = 4; o; o >>= 1) {
        float om = __shfl_xor_sync(0xffffffffu, m, o);
        float os = __shfl_xor_sync(0xffffffffu, s, o);
        pair_combine(m, s, om, os);
    }
}
__device__ __forceinline__ void warp_pair_reduce32(float& m, float& s) {
#pragma unroll
    for (int o = 16; o; o >>= 1) {
        float om = __shfl_xor_sync(0xffffffffu, m, o);
        float os = __shfl_xor_sync(0xffffffffu, s, o);
        pair_combine(m, s, om, os);
    }
}

template <int C4>
__device__ __forceinline__ float row_dot(const float4* __restrict__ row,
                                         const float4* __restrict__ vec, int lane) {
    float s = 0.0f;
#pragma unroll
    for (int i = 0; i < C4 / 32; ++i) {
        float4 w = __ldg(&row[lane + i * 32]);
        float4 x = vec[lane + i * 32];
        s = fmaf(w.x, x.x, s); s = fmaf(w.y, x.y, s);
        s = fmaf(w.z, x.z, s); s = fmaf(w.w, x.w, s);
    }
    return warp_sum(s);
}

// ================= everything in ONE kernel, 5 blocks/SM =================
__global__ void __launch_bounds__(TPB, 5)
fused_kernel(const int* __restrict__ y, const float* __restrict__ s_bef,
             const float* __restrict__ h_all, const float* __restrict__ emb_W,
             const float* __restrict__ alignW, const float* __restrict__ new_W,
             const float* __restrict__ new_b, const float* __restrict__ W_ih,
             const float* __restrict__ b_ih, const float* __restrict__ W_hh,
             const float* __restrict__ b_hh, const float* __restrict__ out_W,
             const float* __restrict__ out_b, float* __restrict__ out) {
    __shared__ float sbuf[2 * H];
    __shared__ float sred[40];
    __shared__ float smp[8], ssp[8];

    const int t    = threadIdx.x;
    const int bid  = blockIdx.x;
    const int wid  = t >> 5;
    const int lane = t & 31;
    const int gw   = bid * 8 + wid;     // 0..5919
    const int r0   = gw * NROW_LOG;     // this warp's phase-5 row base
    float4* sb4 = reinterpret_cast<float4*>(sbuf);

    // ---------- phase 1: e = h_all@Wh (online stats) ; gh = W_hh@s_prev + b_hh ; setup ----------
    sb4[t]       = reinterpret_cast<const float4*>(alignW)[t];        // Wh
    sb4[256 + t] = reinterpret_cast<const float4*>(s_bef)[t];         // s_prev
    __syncthreads();

    if (bid == 1)
        reinterpret_cast<float4*>(g_cat)[t] =
            reinterpret_cast<const float4*>(emb_W)[(size_t)y[0] * 256 + t];
    if (bid == 2)
        reinterpret_cast<float4*>(g_cat)[256 + t] = make_float4(0.f, 0.f, 0.f, 0.f);

    float em = -1e30f, es = 0.0f;                // this warp's online e-stats (fixed order)
    for (int r = gw; r < LCTX + 3 * H; r += NWARP) {
        float s;
        if (r < LCTX)
            s = row_dot<256>(reinterpret_cast<const float4*>(h_all) + (size_t)r * 256, sb4, lane);
        else
            s = row_dot<256>(reinterpret_cast<const float4*>(W_hh) + (size_t)(r - LCTX) * 256, sb4 + 256, lane);
        if (r < LCTX) {
            if (lane == 0) g_e[r] = s;
            pair_combine(em, es, s, 1.0f);       // s is warp-uniform after warp_sum
        } else if (lane == 0) {
            g_gh[r - LCTX] = s + b_hh[r - LCTX];
        }
    }
    if (lane == 0) { smp[wid] = em; ssp[wid] = es; }
    __syncthreads();
    if (wid == 0) {
        float pm = (lane < 8) ? smp[lane] : -1e30f;
        float ps = (lane < 8) ? ssp[lane] : 0.0f;
        warp_pair_reduce8(pm, ps);
        if (lane == 0) { g_bm[bid] = pm; g_bs[bid] = ps; }
    }
    grid_barrier();

    // ---------- phase 2: combine 740 e-stat pairs (fixed order) ; ctx ; a-out ----------
    {
        float pm = -1e30f, ps = 0.0f;
        for (int i = t; i < NBLK; i += TPB) pair_combine(pm, ps, g_bm[i], g_bs[i]);
        warp_pair_reduce32(pm, ps);
        if (lane == 0) { smp[wid] = pm; ssp[wid] = ps; }
        __syncthreads();
        if (wid == 0) {
            float qm = (lane < 8) ? smp[lane] : -1e30f;
            float qs = (lane < 8) ? ssp[lane] : 0.0f;
            warp_pair_reduce8(qm, qs);
            if (lane == 0) { sred[32] = qm; sred[33] = qs; }
        }
        __syncthreads();
    }
    const float M    = sred[32];
    const float invS = 1.0f / sred[33];
    __syncthreads();

    if (bid < 512) {
        // ctx: block = 32 l-rows x 256 cols; h_all re-read is L2-hot
        const int jg = bid & 3, l0 = (bid >> 2) * 32;
        if (t < 32) sbuf[t] = expf(g_e[l0 + t] - M) * invS;
        __syncthreads();
        const int j = jg * 256 + t;
        const float* hp = h_all + (size_t)l0 * H + j;
        float acc = 0.0f;
#pragma unroll 8
        for (int l = 0; l < 32; ++l) acc = fmaf(sbuf[l], hp[(size_t)l * H], acc);
        atomicAdd(&g_cat[H + j], acc);
    } else if (bid < 528) {
        int l = (bid - 512) * 256 + t;
        out[V + H + l] = expf(g_e[l] - M) * invS;   // attention weights output
    }
    grid_barrier();

    // ---------- phase 3: x = new_W @ [emb; c] + new_b  (rows spread over ALL warps: gw = 5r) ----------
    sb4[t]       = reinterpret_cast<const float4*>(g_cat)[t];
    sb4[256 + t] = reinterpret_cast<const float4*>(g_cat)[256 + t];
    __syncthreads();
    {
        const int r = gw / 5;                    // row owned iff gw == 5r (spreads over all SMs)
        if (gw - 5 * r == 0 && r < H) {
            float acc = row_dot<512>(reinterpret_cast<const float4*>(new_W) + (size_t)r * 512, sb4, lane);
            if (lane == 0) g_x[r] = acc + new_b[r];
        }
    }
    grid_barrier();

    // ---------- phase 4: gi rows (3 per owning warp) + GRU gates (same gw = 5r spread) ----------
    sb4[t] = reinterpret_cast<const float4*>(g_x)[t];
    __syncthreads();
    {
        const int r = gw / 5;
        if (gw - 5 * r == 0 && r < H) {
            const float4* Wv = reinterpret_cast<const float4*>(W_ih);
            float d0 = row_dot<256>(Wv + (size_t)r * 256, sb4, lane);
            float d1 = row_dot<256>(Wv + (size_t)(r + H) * 256, sb4, lane);
            float d2 = row_dot<256>(Wv + (size_t)(r + 2 * H) * 256, sb4, lane);
            if (lane == 0) {
                float rr = 1.0f / (1.0f + expf(-(d0 + b_ih[r] + g_gh[r])));
                float zz = 1.0f / (1.0f + expf(-(d1 + b_ih[r + H] + g_gh[r + H])));
                float nn = tanhf(d2 + b_ih[r + 2 * H] + rr * g_gh[r + 2 * H]);
                float hv = (1.0f - zz) * nn + zz * s_bef[r];
                g_h[r]    = hv;
                out[V + r] = hv;
            }
        }
    }
    grid_barrier();

    // ---------- phase 5: logits GEMV, 9 consecutive rows/warp, __ldcs stream ----------
    sb4[t] = reinterpret_cast<const float4*>(g_h)[t];
    __syncthreads();

    float vals[NROW_LOG];
#pragma unroll
    for (int k = 0; k < NROW_LOG; ++k) {
        const int r = r0 + k;
        float s = 0.0f;
        if (r < V) {
            const float4* Wr = reinterpret_cast<const float4*>(out_W) + (size_t)r * 256;
#pragma unroll
            for (int i = 0; i < 8; ++i) {
                float4 w = __ldcs(&Wr[lane + i * 32]);
                float4 x = sb4[lane + i * 32];
                s = fmaf(w.x, x.x, s); s = fmaf(w.y, x.y, s);
                s = fmaf(w.z, x.z, s); s = fmaf(w.w, x.w, s);
            }
        }
        vals[k] = s;
    }
#pragma unroll
    for (int k = 0; k < NROW_LOG; ++k) {
        vals[k] = warp_sum(vals[k]);
        if (r0 + k < V) vals[k] += out_b[r0 + k];
    }
    float lm = -1e30f, ls = 0.0f;
#pragma unroll
    for (int k = 0; k < NROW_LOG; ++k)
        if (r0 + k < V) pair_combine(lm, ls, vals[k], 1.0f);

    if (lane == 0) { smp[wid] = lm; ssp[wid] = ls; }
    __syncthreads();
    if (wid == 0) {
        float pm = (lane < 8) ? smp[lane] : -1e30f;
        float ps = (lane < 8) ? ssp[lane] : 0.0f;
        warp_pair_reduce8(pm, ps);
        if (lane == 0) { g_bm[bid] = pm; g_bs[bid] = ps; }
    }
    grid_barrier();

    // ---------- phase 6: combine 740 block pairs redundantly; store final logp ----------
    {
        float pm = -1e30f, ps = 0.0f;
        for (int i = t; i < NBLK; i += TPB) pair_combine(pm, ps, g_bm[i], g_bs[i]);
        warp_pair_reduce32(pm, ps);
        if (lane == 0) { smp[wid] = pm; ssp[wid] = ps; }
        __syncthreads();
        if (wid == 0) {
            float qm = (lane < 8) ? smp[lane] : -1e30f;
            float qs = (lane < 8) ? ssp[lane] : 0.0f;
            warp_pair_reduce8(qm, qs);
            if (lane == 0) sred[34] = qm + logf(qs);
        }
        __syncthreads();
        const float ln = sred[34];
        if (lane == 0) {
#pragma unroll
            for (int k = 0; k < NROW_LOG; ++k)
                if (r0 + k < V) out[r0 + k] = vals[k] - ln;   // only store of logits
        }
    }
}

// ================= launch: single kernel =================
extern "C" void kernel_launch(void* const* d_in, const int* in_sizes, int n_in,
                              void* d_out, int out_size) {
    const int*   y      = (const int*)d_in[0];
    const float* s_bef  = (const float*)d_in[1];
    const float* h_all  = (const float*)d_in[2];
    const float* emb_W  = (const float*)d_in[3];
    const float* alignW = (const float*)d_in[4];
    // d_in[5] align_b: uniform additive shift -> softmax-invariant, dropped
    const float* new_W  = (const float*)d_in[6];
    const float* new_b  = (const float*)d_in[7];
    const float* W_ih   = (const float*)d_in[8];
    const float* b_ih   = (const float*)d_in[9];
    const float* W_hh   = (const float*)d_in[10];
    const float* b_hh   = (const float*)d_in[11];
    const float* out_W  = (const float*)d_in[12];
    const float* out_b  = (const float*)d_in[13];
    float* out = (float*)d_out;  // [logp(V) | h_new(H) | a(L)]

    fused_kernel<<<NBLK, TPB>>>(y, s_bef, h_all, emb_W, alignW, new_W, new_b,
                                W_ih, b_ih, W_hh, b_hh, out_W, out_b, out);
}

// round 17
// speedup vs baseline: 1.1186x; 1.0537x over previous
#include <cuda_runtime.h>

#define H 1024
#define V 50257
#define LCTX 4096

#define NBLK 740            // 148 SMs x 5 co-resident 256-thr blocks -> sw barrier safe
#define TPB  256
#define NWARP (NBLK * 8)    // 5920 warps
#define NROW_LOG 9          // ceil(V / NWARP), consecutive rows per warp

// ---------------- device scratch (allocation-free, 16B aligned) ----------------
__device__ __align__(16) float g_e[LCTX];
__device__ __align__(16) float g_cat[2 * H];
__device__ __align__(16) float g_x[H];
__device__ __align__(16) float g_gh[3 * H];
__device__ __align__(16) float g_h[H];
__device__ float g_bm[NBLK];
__device__ float g_bs[NBLK];
__device__ unsigned g_bar_count = 0;
__device__ unsigned g_bar_gen   = 0;    // gen-counting protocol: safe across launches/replays

__device__ __forceinline__ void grid_barrier() {
    __threadfence();
    __syncthreads();
    if (threadIdx.x == 0) {
        unsigned gen = *(volatile unsigned*)&g_bar_gen;
        if (atomicAdd(&g_bar_count, 1u) == NBLK - 1) {
            g_bar_count = 0;
            __threadfence();
            atomicExch(&g_bar_gen, gen + 1);
        } else {
            while (*(volatile unsigned*)&g_bar_gen == gen) { __nanosleep(64); }
        }
        __threadfence();
    }
    __syncthreads();
}

__device__ __forceinline__ float warp_sum(float s) {
#pragma unroll
    for (int o = 16; o; o >>= 1) s += __shfl_xor_sync(0xffffffffu, s, o);
    return s;
}
__device__ __forceinline__ void pair_combine(float& m, float& s, float om, float os) {
    float nm = fmaxf(m, om);
    s = s * expf(m - nm) + os * expf(om - nm);
    m = nm;
}
__device__ __forceinline__ void warp_pair_reduce8(float& m, float& s) {
#pragma unroll
    for (int o = 4; o; o >>= 1) {
        float om = __shfl_xor_sync(0xffffffffu, m, o);
        float os = __shfl_xor_sync(0xffffffffu, s, o);
        pair_combine(m, s, om, os);
    }
}
__device__ __forceinline__ void warp_pair_reduce32(float& m, float& s) {
#pragma unroll
    for (int o = 16; o; o >>= 1) {
        float om = __shfl_xor_sync(0xffffffffu, m, o);
        float os = __shfl_xor_sync(0xffffffffu, s, o);
        pair_combine(m, s, om, os);
    }
}

template <int C4>
__device__ __forceinline__ float row_dot(const float4* __restrict__ row,
                                         const float4* __restrict__ vec, int lane) {
    float s = 0.0f;
#pragma unroll
    for (int i = 0; i < C4 / 32; ++i) {
        float4 w = __ldg(&row[lane + i * 32]);
        float4 x = vec[lane + i * 32];
        s = fmaf(w.x, x.x, s); s = fmaf(w.y, x.y, s);
        s = fmaf(w.z, x.z, s); s = fmaf(w.w, x.w, s);
    }
    return warp_sum(s);
}

// ================= kernel A: phases 1-4 (attention + GRU chain) =================
__global__ void __launch_bounds__(TPB, 5)
chain_kernel(const int* __restrict__ y, const float* __restrict__ s_bef,
             const float* __restrict__ h_all, const float* __restrict__ emb_W,
             const float* __restrict__ alignW, const float* __restrict__ new_W,
             const float* __restrict__ new_b, const float* __restrict__ W_ih,
             const float* __restrict__ b_ih, const float* __restrict__ W_hh,
             const float* __restrict__ b_hh, float* __restrict__ out) {
    __shared__ float sbuf[2 * H];
    __shared__ float sred[40];
    __shared__ float smp[8], ssp[8];

    const int t    = threadIdx.x;
    const int bid  = blockIdx.x;
    const int wid  = t >> 5;
    const int lane = t & 31;
    const int gw   = bid * 8 + wid;
    float4* sb4 = reinterpret_cast<float4*>(sbuf);

    // ---------- phase 1: e = h_all@Wh (online stats) ; gh = W_hh@s_prev + b_hh ; setup ----------
    sb4[t]       = reinterpret_cast<const float4*>(alignW)[t];        // Wh
    sb4[256 + t] = reinterpret_cast<const float4*>(s_bef)[t];         // s_prev
    __syncthreads();

    if (bid == 1)
        reinterpret_cast<float4*>(g_cat)[t] =
            reinterpret_cast<const float4*>(emb_W)[(size_t)y[0] * 256 + t];
    if (bid == 2)
        reinterpret_cast<float4*>(g_cat)[256 + t] = make_float4(0.f, 0.f, 0.f, 0.f);

    float em = -1e30f, es = 0.0f;
    for (int r = gw; r < LCTX + 3 * H; r += NWARP) {
        float s;
        if (r < LCTX)
            s = row_dot<256>(reinterpret_cast<const float4*>(h_all) + (size_t)r * 256, sb4, lane);
        else
            s = row_dot<256>(reinterpret_cast<const float4*>(W_hh) + (size_t)(r - LCTX) * 256, sb4 + 256, lane);
        if (r < LCTX) {
            if (lane == 0) g_e[r] = s;
            pair_combine(em, es, s, 1.0f);
        } else if (lane == 0) {
            g_gh[r - LCTX] = s + b_hh[r - LCTX];
        }
    }
    if (lane == 0) { smp[wid] = em; ssp[wid] = es; }
    __syncthreads();
    if (wid == 0) {
        float pm = (lane < 8) ? smp[lane] : -1e30f;
        float ps = (lane < 8) ? ssp[lane] : 0.0f;
        warp_pair_reduce8(pm, ps);
        if (lane == 0) { g_bm[bid] = pm; g_bs[bid] = ps; }
    }
    grid_barrier();

    // ---------- phase 2: combine 740 e-stat pairs ; ctx ; a-out ----------
    {
        float pm = -1e30f, ps = 0.0f;
        for (int i = t; i < NBLK; i += TPB) pair_combine(pm, ps, g_bm[i], g_bs[i]);
        warp_pair_reduce32(pm, ps);
        if (lane == 0) { smp[wid] = pm; ssp[wid] = ps; }
        __syncthreads();
        if (wid == 0) {
            float qm = (lane < 8) ? smp[lane] : -1e30f;
            float qs = (lane < 8) ? ssp[lane] : 0.0f;
            warp_pair_reduce8(qm, qs);
            if (lane == 0) { sred[32] = qm; sred[33] = qs; }
        }
        __syncthreads();
    }
    const float M    = sred[32];
    const float invS = 1.0f / sred[33];
    __syncthreads();

    if (bid < 512) {
        const int jg = bid & 3, l0 = (bid >> 2) * 32;
        if (t < 32) sbuf[t] = expf(g_e[l0 + t] - M) * invS;
        __syncthreads();
        const int j = jg * 256 + t;
        const float* hp = h_all + (size_t)l0 * H + j;
        float acc = 0.0f;
#pragma unroll 8
        for (int l = 0; l < 32; ++l) acc = fmaf(sbuf[l], hp[(size_t)l * H], acc);
        atomicAdd(&g_cat[H + j], acc);
    } else if (bid < 528) {
        int l = (bid - 512) * 256 + t;
        out[V + H + l] = expf(g_e[l] - M) * invS;   // attention weights output
    }
    grid_barrier();

    // ---------- phase 3: x = new_W @ [emb; c] + new_b ----------
    if (bid < 128) {
        sb4[t]       = reinterpret_cast<const float4*>(g_cat)[t];
        sb4[256 + t] = reinterpret_cast<const float4*>(g_cat)[256 + t];
        __syncthreads();
        float acc = row_dot<512>(reinterpret_cast<const float4*>(new_W) + (size_t)gw * 512, sb4, lane);
        if (lane == 0) g_x[gw] = acc + new_b[gw];
    }
    grid_barrier();

    // ---------- phase 4: gi rows (3 per warp) fused with GRU gates -> h_new ----------
    if (bid < 128) {
        sb4[t] = reinterpret_cast<const float4*>(g_x)[t];
        __syncthreads();
        const float4* Wv = reinterpret_cast<const float4*>(W_ih);
        float d0 = row_dot<256>(Wv + (size_t)gw * 256, sb4, lane);
        float d1 = row_dot<256>(Wv + (size_t)(gw + H) * 256, sb4, lane);
        float d2 = row_dot<256>(Wv + (size_t)(gw + 2 * H) * 256, sb4, lane);
        if (lane == 0) {
            float rr = 1.0f / (1.0f + expf(-(d0 + b_ih[gw] + g_gh[gw])));
            float zz = 1.0f / (1.0f + expf(-(d1 + b_ih[gw + H] + g_gh[gw + H])));
            float nn = tanhf(d2 + b_ih[gw + 2 * H] + rr * g_gh[gw + 2 * H]);
            float hv = (1.0f - zz) * nn + zz * s_bef[gw];
            g_h[gw]    = hv;
            out[V + gw] = hv;
        }
    }
    // kernel end = implicit device-wide sync before logits_kernel
}

// ================= kernel B: phase 5+6 (logits GEMV + fused log-softmax) =================
__global__ void __launch_bounds__(TPB, 5)
logits_kernel(const float* __restrict__ out_W, const float* __restrict__ out_b,
              float* __restrict__ out) {
    __shared__ float sbuf[2 * H];
    __shared__ float sred[40];
    __shared__ float smp[8], ssp[8];

    const int t    = threadIdx.x;
    const int bid  = blockIdx.x;
    const int wid  = t >> 5;
    const int lane = t & 31;
    const int gw   = bid * 8 + wid;
    const int r0   = gw * NROW_LOG;
    float4* sb4 = reinterpret_cast<float4*>(sbuf);

    sb4[t] = reinterpret_cast<const float4*>(g_h)[t];
    __syncthreads();

    float vals[NROW_LOG];
#pragma unroll
    for (int k = 0; k < NROW_LOG; ++k) {
        const int r = r0 + k;
        float s = 0.0f;
        if (r < V) {
            const float4* Wr = reinterpret_cast<const float4*>(out_W) + (size_t)r * 256;
#pragma unroll
            for (int i = 0; i < 8; ++i) {
                float4 w = __ldcs(&Wr[lane + i * 32]);
                float4 x = sb4[lane + i * 32];
                s = fmaf(w.x, x.x, s); s = fmaf(w.y, x.y, s);
                s = fmaf(w.z, x.z, s); s = fmaf(w.w, x.w, s);
            }
        }
        vals[k] = s;
    }
#pragma unroll
    for (int k = 0; k < NROW_LOG; ++k) {
        vals[k] = warp_sum(vals[k]);
        if (r0 + k < V) vals[k] += out_b[r0 + k];
    }
    float lm = -1e30f, ls = 0.0f;
#pragma unroll
    for (int k = 0; k < NROW_LOG; ++k)
        if (r0 + k < V) pair_combine(lm, ls, vals[k], 1.0f);

    if (lane == 0) { smp[wid] = lm; ssp[wid] = ls; }
    __syncthreads();
    if (wid == 0) {
        float pm = (lane < 8) ? smp[lane] : -1e30f;
        float ps = (lane < 8) ? ssp[lane] : 0.0f;
        warp_pair_reduce8(pm, ps);
        if (lane == 0) { g_bm[bid] = pm; g_bs[bid] = ps; }
    }
    grid_barrier();

    {
        float pm = -1e30f, ps = 0.0f;
        for (int i = t; i < NBLK; i += TPB) pair_combine(pm, ps, g_bm[i], g_bs[i]);
        warp_pair_reduce32(pm, ps);
        if (lane == 0) { smp[wid] = pm; ssp[wid] = ps; }
        __syncthreads();
        if (wid == 0) {
            float qm = (lane < 8) ? smp[lane] : -1e30f;
            float qs = (lane < 8) ? ssp[lane] : 0.0f;
            warp_pair_reduce8(qm, qs);
            if (lane == 0) sred[34] = qm + logf(qs);
        }
        __syncthreads();
        const float ln = sred[34];
        if (lane == 0) {
#pragma unroll
            for (int k = 0; k < NROW_LOG; ++k)
                if (r0 + k < V) out[r0 + k] = vals[k] - ln;   // only store of logits
        }
    }
}

// ================= launch: two kernels =================
extern "C" void kernel_launch(void* const* d_in, const int* in_sizes, int n_in,
                              void* d_out, int out_size) {
    const int*   y      = (const int*)d_in[0];
    const float* s_bef  = (const float*)d_in[1];
    const float* h_all  = (const float*)d_in[2];
    const float* emb_W  = (const float*)d_in[3];
    const float* alignW = (const float*)d_in[4];
    // d_in[5] align_b: uniform additive shift -> softmax-invariant, dropped
    const float* new_W  = (const float*)d_in[6];
    const float* new_b  = (const float*)d_in[7];
    const float* W_ih   = (const float*)d_in[8];
    const float* b_ih   = (const float*)d_in[9];
    const float* W_hh   = (const float*)d_in[10];
    const float* b_hh   = (const float*)d_in[11];
    const float* out_W  = (const float*)d_in[12];
    const float* out_b  = (const float*)d_in[13];
    float* out = (float*)d_out;  // [logp(V) | h_new(H) | a(L)]

    chain_kernel<<<NBLK, TPB>>>(y, s_bef, h_all, emb_W, alignW, new_W, new_b,
                                W_ih, b_ih, W_hh, b_hh, out);
    logits_kernel<<<NBLK, TPB>>>(out_W, out_b, out);
}